// round 7
// baseline (speedup 1.0000x reference)
#include <cuda_runtime.h>
#include <math.h>

// Problem constants
#define Bb 16
#define Tt 16
#define Cc 64
#define HD 64
#define HW 1024
#define IMW 32
#define NT 128
#define SROW 36
#define PLANE (34*SROW)   // 1224 floats per padded plane

// Scratch (device globals: no allocation allowed)
__device__ float g_h   [Bb*HD*HW];
__device__ float g_hode[Bb*HD*HW];
__device__ float g_rh  [Bb*HD*HW];
__device__ float g_u   [Bb*HD*HW];
__device__ float g_gx  [(size_t)Tt*Bb*2*HD*HW];   // x-part of gates conv (+bias)
__device__ float g_cx  [(size_t)Tt*Bb*HD*HW];     // x-part of cand conv (+bias)

// ---------------------------------------------------------------------------
// Core: 3x3 SAME conv over NCI input channels starting at ci0, one 32x32
// image, 4 output channels, 8 px/thread, 128 threads cooperating (tid 0..127).
// ws/pl are caller-provided smem regions (so two halves of a 256-thread CTA
// can run disjoint instances). Weights padded to 12 floats per (oc,ci).
// NOTE: __syncthreads() inside synchronizes the WHOLE CTA — all participating
// halves must call with identical trip counts.
// ---------------------------------------------------------------------------
template<int NCI>
__device__ __forceinline__ void conv_core(
    const float* __restrict__ in,     // image base [64][1024]
    const float* __restrict__ wsrc,   // per-oc row stride = wstride9 floats
    int wstride9, int ocb, int ci0,
    float* ws, float* pl, int tid,
    float acc[4][8])
{
    const int row = tid >> 2;          // 0..31
    const int xb  = (tid & 3) << 3;    // 0,8,16,24

    // Stage weights: ws[(oc*NCI+ci)*12 + tap], taps 9..11 zero-padded
    for (int i = tid; i < 4*NCI*12; i += NT) {
        const int tap = i % 12;
        const int ci_ = (i / 12) % NCI;
        const int oc_ = i / (12*NCI);
        ws[i] = (tap < 9)
              ? wsrc[(size_t)(ocb*4 + oc_)*wstride9 + (ci0 + ci_)*9 + tap] : 0.f;
    }
    for (int i = tid; i < 4*PLANE; i += NT) pl[i] = 0.f;

    const float* inp = in + (size_t)ci0*HW;
    const int goff = row*IMW + xb;
    float4 n0a = *reinterpret_cast<const float4*>(inp + goff);
    float4 n0b = *reinterpret_cast<const float4*>(inp + goff + 4);
    float4 n1a = *reinterpret_cast<const float4*>(inp + HW + goff);
    float4 n1b = *reinterpret_cast<const float4*>(inp + HW + goff + 4);
    __syncthreads();   // zero/weights visible before interior stores

    #pragma unroll 1
    for (int pr = 0; pr < NCI/2; pr++) {
        float* b0 = pl + (pr & 1)*2*PLANE;
        float* b1 = b0 + PLANE;
        {
            float* d0 = b0 + (row + 1)*SROW + xb + 1;
            d0[0]=n0a.x; d0[1]=n0a.y; d0[2]=n0a.z; d0[3]=n0a.w;
            d0[4]=n0b.x; d0[5]=n0b.y; d0[6]=n0b.z; d0[7]=n0b.w;
            float* d1 = b1 + (row + 1)*SROW + xb + 1;
            d1[0]=n1a.x; d1[1]=n1a.y; d1[2]=n1a.z; d1[3]=n1a.w;
            d1[4]=n1b.x; d1[5]=n1b.y; d1[6]=n1b.z; d1[7]=n1b.w;
        }
        __syncthreads();
        if (pr < NCI/2 - 1) {
            const float* g = inp + (2*pr + 2)*HW + goff;
            n0a = *reinterpret_cast<const float4*>(g);
            n0b = *reinterpret_cast<const float4*>(g + 4);
            n1a = *reinterpret_cast<const float4*>(g + HW);
            n1b = *reinterpret_cast<const float4*>(g + HW + 4);
        }
        #pragma unroll
        for (int half = 0; half < 2; half++) {
            const float* cur = half ? b1 : b0;
            const int ci = 2*pr + half;
            float p[3][10];
            #pragma unroll
            for (int r = 0; r < 3; r++) {
                const float* s = cur + (row + r)*SROW + xb;   // 16B aligned
                float4 a = *reinterpret_cast<const float4*>(s);
                float4 b = *reinterpret_cast<const float4*>(s + 4);
                float2 c = *reinterpret_cast<const float2*>(s + 8);
                p[r][0]=a.x; p[r][1]=a.y; p[r][2]=a.z; p[r][3]=a.w;
                p[r][4]=b.x; p[r][5]=b.y; p[r][6]=b.z; p[r][7]=b.w;
                p[r][8]=c.x; p[r][9]=c.y;
            }
            #pragma unroll
            for (int oc = 0; oc < 4; oc++) {
                const float4* wp = reinterpret_cast<const float4*>(ws + (oc*NCI + ci)*12);
                float4 wA = wp[0];
                float4 wB = wp[1];
                float  w8 = ws[(oc*NCI + ci)*12 + 8];
                #pragma unroll
                for (int px = 0; px < 8; px++) {
                    acc[oc][px] += p[0][px]*wA.x + p[0][px+1]*wA.y + p[0][px+2]*wA.z
                                 + p[1][px]*wA.w + p[1][px+1]*wB.x + p[1][px+2]*wB.y
                                 + p[2][px]*wB.z + p[2][px+1]*wB.w + p[2][px+2]*w8;
                }
            }
        }
    }
}

__device__ __forceinline__ float sigmoidf_(float x) { return 1.f / (1.f + expf(-x)); }

__device__ __forceinline__ void st8(float* o, const float a[8]) {
    *reinterpret_cast<float4*>(o)     = make_float4(a[0],a[1],a[2],a[3]);
    *reinterpret_cast<float4*>(o + 4) = make_float4(a[4],a[5],a[6],a[7]);
}

// ---------------------------------------------------------------------------
// Precompute x-contributions: out[t][b][co][pix] = conv(x_{T-1-t}) + bias
// grid = (cout/4, T*B), 128 threads
// ---------------------------------------------------------------------------
__global__ void __launch_bounds__(NT, 5) k_pre(
    const float* __restrict__ x0, const float* __restrict__ w, int wstride9,
    const float* __restrict__ bias, float* __restrict__ out, int cout)
{
    extern __shared__ float smem[];
    const int ocb = blockIdx.x, z = blockIdx.y;
    const int t = z >> 4, b = z & 15;
    const float* in = x0 + ((size_t)(b*Tt + (Tt-1-t))*Cc)*HW;

    float acc[4][8];
    #pragma unroll
    for (int oc = 0; oc < 4; oc++) {
        float bv = bias[ocb*4 + oc];
        #pragma unroll
        for (int px = 0; px < 8; px++) acc[oc][px] = bv;
    }
    conv_core<64>(in, w, wstride9, ocb, 0, smem, smem + 4*768, threadIdx.x, acc);

    const int row = threadIdx.x >> 2, xb = (threadIdx.x & 3) << 3;
    float* o = out + ((size_t)(t*Bb + b)*cout + ocb*4)*HW + row*IMW + xb;
    #pragma unroll
    for (int oc = 0; oc < 4; oc++) st8(o + oc*HW, acc[oc]);
}

// ---------------------------------------------------------------------------
// Split-ci step kernel (256 threads): warps 0-3 convolve ci 0..31, warps 4-7
// convolve ci 32..63, partials combined through smem, epilogue fused.
// MODE 0: ODE  (src g_h,  out g_hode = h + tanh(conv+b)*dt)
// MODE 1: CAND (src g_rh, out g_h = ho + m*u*(tanh(conv+cx)-ho))
// grid = (16, B). smem: ws[2*1536] | planes[2*4896] (pbuf overlaps planes[0]).
// ---------------------------------------------------------------------------
template<int MODE>
__global__ void __launch_bounds__(256, 2) k_step(
    const float* __restrict__ wsrc, int wstride9,
    const float* __restrict__ aux,      // MODE0: bias; MODE1: mask
    const float* __restrict__ ts, int step)
{
    extern __shared__ float smem[];
    const int ocb = blockIdx.x, b = blockIdx.y;
    const int tid  = threadIdx.x;
    const int half = tid >> 7;          // 0 or 1
    const int htid = tid & 127;

    float* ws = smem + half*1536;                 // 4 oc x 32 ci x 12
    float* pl = smem + 3072 + half*(4*PLANE);     // 4 planes per half
    float* pbuf = smem + 3072;                    // overlaps half0's planes

    const float* src = (MODE == 0 ? g_h : g_rh) + (size_t)b*HD*HW;

    float acc[4][8];
    #pragma unroll
    for (int oc = 0; oc < 4; oc++)
        #pragma unroll
        for (int px = 0; px < 8; px++) acc[oc][px] = 0.f;

    conv_core<32>(src, wsrc, wstride9, ocb, half*32, ws, pl, htid, acc);

    __syncthreads();   // all plane reads done before pbuf overwrites planes

    const int row = htid >> 2, xb = (htid & 3) << 3;
    if (half == 1) {
        #pragma unroll
        for (int oc = 0; oc < 4; oc++)
            st8(pbuf + oc*HW + row*IMW + xb, acc[oc]);
    }
    __syncthreads();

    if (half == 0) {
        if (MODE == 0) {
            const float dt = (step == 0) ? -0.01f : (ts[Tt-1-step] - ts[Tt-step]);
            #pragma unroll
            for (int oc = 0; oc < 4; oc++) {
                const float bv = aux[ocb*4 + oc];
                const float* pb = pbuf + oc*HW + row*IMW + xb;
                size_t ib = ((size_t)b*HD + ocb*4 + oc)*HW + row*IMW + xb;
                float r[8];
                #pragma unroll
                for (int px = 0; px < 8; px++)
                    r[px] = g_h[ib + px] + tanhf(acc[oc][px] + pb[px] + bv)*dt;
                st8(&g_hode[ib], r);
            }
        } else {
            const float m = aux[b*Tt + (Tt-1-step)];
            const float* pre = g_cx + ((size_t)(step*Bb + b)*HD + ocb*4)*HW + row*IMW + xb;
            #pragma unroll
            for (int oc = 0; oc < 4; oc++) {
                const float* pb = pbuf + oc*HW + row*IMW + xb;
                size_t ib = ((size_t)b*HD + ocb*4 + oc)*HW + row*IMW + xb;
                float r[8];
                #pragma unroll
                for (int px = 0; px < 8; px++) {
                    float ho = g_hode[ib + px];
                    float c  = tanhf(acc[oc][px] + pb[px] + pre[oc*HW + px]);
                    r[px] = ho + m*g_u[ib + px]*(c - ho);
                }
                st8(&g_h[ib], r);
            }
        }
    }
}

// ---------------------------------------------------------------------------
// Gates: g = sigmoid(conv(h_ode)+gx).  co<64 -> rh = g*h_ode; else u = g.
// grid = (32, B), 128 threads
// ---------------------------------------------------------------------------
__global__ void __launch_bounds__(NT, 5) k_gates(const float* __restrict__ w, int step)
{
    extern __shared__ float smem[];
    const int ocb = blockIdx.x, b = blockIdx.y;
    const float* in = g_hode + (size_t)b*HD*HW;

    float acc[4][8];
    #pragma unroll
    for (int oc = 0; oc < 4; oc++)
        #pragma unroll
        for (int px = 0; px < 8; px++) acc[oc][px] = 0.f;
    conv_core<64>(in, w, 1152, ocb, 0, smem, smem + 4*768, threadIdx.x, acc);

    const int row = threadIdx.x >> 2, xb = (threadIdx.x & 3) << 3;
    const int co0 = ocb*4;
    const float* pre = g_gx + ((size_t)(step*Bb + b)*(2*HD) + co0)*HW + row*IMW + xb;
    #pragma unroll
    for (int oc = 0; oc < 4; oc++) {
        float g[8];
        #pragma unroll
        for (int px = 0; px < 8; px++)
            g[px] = sigmoidf_(acc[oc][px] + pre[oc*HW + px]);
        if (co0 < HD) {
            size_t ib = ((size_t)b*HD + co0 + oc)*HW + row*IMW + xb;
            #pragma unroll
            for (int px = 0; px < 8; px++) g[px] *= g_hode[ib + px];
            st8(&g_rh[ib], g);
        } else {
            size_t ib = ((size_t)b*HD + co0 - HD + oc)*HW + row*IMW + xb;
            st8(&g_u[ib], g);
        }
    }
}

// ---------------------------------------------------------------------------
// Head: z1 = relu(W1 h + b1); z2 = W2 z1 + b2; out = [z2[:64] ; |z2[64:]|]
// grid = (4, B)
// ---------------------------------------------------------------------------
__global__ void __launch_bounds__(256) k_final(
    const float* __restrict__ w1, const float* __restrict__ b1,
    const float* __restrict__ w2, const float* __restrict__ b2,
    float* __restrict__ out)
{
    extern __shared__ float smem[];
    float* w1s = smem;          // [64][64]
    float* w2s = smem + 4096;   // [128][64]
    const int tid = threadIdx.x, pb = blockIdx.x, b = blockIdx.y;
    for (int i = tid; i < 4096; i += 256) w1s[i] = w1[i];
    for (int i = tid; i < 8192; i += 256) w2s[i] = w2[i];
    __syncthreads();

    const int pix = pb*256 + tid;
    float z1[64];
    #pragma unroll
    for (int co = 0; co < 64; co++) z1[co] = b1[co];
    for (int ci = 0; ci < 64; ci++) {
        float hv = g_h[((size_t)b*HD + ci)*HW + pix];
        #pragma unroll
        for (int co = 0; co < 64; co++) z1[co] += w1s[co*64 + ci]*hv;
    }
    #pragma unroll
    for (int co = 0; co < 64; co++) z1[co] = fmaxf(z1[co], 0.f);

    for (int co2 = 0; co2 < 128; co2++) {
        float a = b2[co2];
        #pragma unroll
        for (int ci = 0; ci < 64; ci++) a += w2s[co2*64 + ci]*z1[ci];
        if (co2 < 64)
            out[((size_t)b*HD + co2)*HW + pix] = a;
        else
            out[(size_t)Bb*HD*HW + ((size_t)b*HD + (co2 - 64))*HW + pix] = fabsf(a);
    }
}

// ---------------------------------------------------------------------------
extern "C" void kernel_launch(void* const* d_in, const int* in_sizes, int n_in,
                              void* d_out, int out_size)
{
    const float* input   = (const float*)d_in[0];
    const float* ts      = (const float*)d_in[1];
    const float* mask    = (const float*)d_in[2];
    const float* w_gates = (const float*)d_in[3];
    const float* b_gates = (const float*)d_in[4];
    const float* w_can   = (const float*)d_in[5];
    const float* b_can   = (const float*)d_in[6];
    const float* w_ode   = (const float*)d_in[7];
    const float* b_ode   = (const float*)d_in[8];
    const float* w_t1    = (const float*)d_in[9];
    const float* b_t1    = (const float*)d_in[10];
    const float* w_t2    = (const float*)d_in[11];
    const float* b_t2    = (const float*)d_in[12];
    float* out = (float*)d_out;

    float *hptr, *gxp, *cxp;
    cudaGetSymbolAddress((void**)&hptr, g_h);
    cudaGetSymbolAddress((void**)&gxp,  g_gx);
    cudaGetSymbolAddress((void**)&cxp,  g_cx);

    cudaMemsetAsync(hptr, 0, (size_t)Bb*HD*HW*sizeof(float));

    const int SM64 = (4*768 + 4*PLANE) * (int)sizeof(float);            // 31872 B
    const int SMS  = (2*1536 + 2*4*PLANE) * (int)sizeof(float);         // 51456 B

    static int smem_set = 0;
    if (!smem_set) {
        cudaFuncSetAttribute(k_step<0>, cudaFuncAttributeMaxDynamicSharedMemorySize, SMS);
        cudaFuncSetAttribute(k_step<1>, cudaFuncAttributeMaxDynamicSharedMemorySize, SMS);
        smem_set = 1;
    }

    k_pre<<<dim3(32, Tt*Bb), NT, SM64>>>(input, w_gates, 1152, b_gates, gxp, 2*HD);
    k_pre<<<dim3(16, Tt*Bb), NT, SM64>>>(input, w_can,   1152, b_can,   cxp, HD);

    for (int s = 0; s < Tt; s++) {
        k_step<0><<<dim3(16, Bb), 256, SMS>>>(w_ode,         576,  b_ode, ts, s);
        k_gates  <<<dim3(32, Bb), NT,  SM64>>>(w_gates + 64*9, s);
        k_step<1><<<dim3(16, Bb), 256, SMS>>>(w_can + 64*9,  1152, mask,  ts, s);
    }

    k_final<<<dim3(4, Bb), 256, 12288*(int)sizeof(float)>>>(w_t1, b_t1, w_t2, b_t2, out);
}